// round 1
// baseline (speedup 1.0000x reference)
#include <cuda_runtime.h>

#define N_USERS 17449
#define N_ITEMS 48676
#define N_NODES (N_USERS + N_ITEMS)   // 66125
#define D_IN    64
#define HC      128                    // H*C = 2*64
#define E_EDGES 2000000
#define NEG_SLOPE 0.2f

// Scratch (no cudaMalloc allowed): ~34.4 MB of __device__ globals.
__device__ float g_h[(size_t)N_NODES * HC];     // transformed features [N,128]
__device__ float g_asrc[N_NODES * 2];           // per-node src logits [N,H]
__device__ float g_adst[N_NODES * 2];           // per-node dst logits [N,H]
__device__ float g_denom[N_NODES * 2];          // softmax denominators [N,H]

// ---------------------------------------------------------------------------
// K0: zero out + denom (d_out is poisoned to 0xAA by the harness)
// ---------------------------------------------------------------------------
__global__ void zero_kernel(float* __restrict__ out) {
    int stride = gridDim.x * blockDim.x;
    for (int i = blockIdx.x * blockDim.x + threadIdx.x; i < N_NODES * HC; i += stride)
        out[i] = 0.0f;
    for (int j = blockIdx.x * blockDim.x + threadIdx.x; j < N_NODES * 2; j += stride)
        g_denom[j] = 0.0f;
}

// ---------------------------------------------------------------------------
// K1: h = x @ W  (x = concat(users, items)), fused a_src/a_dst reductions.
// 128 threads/block, 32 rows/block. W (32 KB) staged in smem once per block.
// ---------------------------------------------------------------------------
#define ROWS_PER_BLOCK 32

__global__ __launch_bounds__(128) void gemm_kernel(
    const float* __restrict__ users,
    const float* __restrict__ items,
    const float* __restrict__ W,        // [64,128] row-major
    const float* __restrict__ att_src,  // [2,64] flattened = 128
    const float* __restrict__ att_dst)
{
    __shared__ float Ws[D_IN * HC];     // 32 KB
    __shared__ float xs[D_IN];
    __shared__ float wsum_s[4], wsum_d[4];

    int tid = threadIdx.x;              // = output column j, j = head*64 + c
    for (int i = tid; i < D_IN * HC; i += 128) Ws[i] = W[i];
    float as = att_src[tid];
    float ad = att_dst[tid];

    int row0 = blockIdx.x * ROWS_PER_BLOCK;
    __syncthreads();

    for (int rr = 0; rr < ROWS_PER_BLOCK; rr++) {
        int n = row0 + rr;
        if (n >= N_NODES) break;

        if (tid < D_IN) {
            xs[tid] = (n < N_USERS) ? users[(size_t)n * D_IN + tid]
                                    : items[(size_t)(n - N_USERS) * D_IN + tid];
        }
        __syncthreads();

        float acc = 0.0f;
        #pragma unroll
        for (int k = 0; k < D_IN; k++)
            acc = fmaf(xs[k], Ws[k * HC + tid], acc);

        g_h[(size_t)n * HC + tid] = acc;

        // attention logit partials; warps 0,1 cover head 0; warps 2,3 head 1
        float ps = acc * as;
        float pd = acc * ad;
        #pragma unroll
        for (int o = 16; o > 0; o >>= 1) {
            ps += __shfl_down_sync(0xffffffffu, ps, o);
            pd += __shfl_down_sync(0xffffffffu, pd, o);
        }
        int w = tid >> 5;
        if ((tid & 31) == 0) { wsum_s[w] = ps; wsum_d[w] = pd; }
        __syncthreads();
        if (tid == 0) {
            g_asrc[n * 2 + 0] = wsum_s[0] + wsum_s[1];
            g_asrc[n * 2 + 1] = wsum_s[2] + wsum_s[3];
            g_adst[n * 2 + 0] = wsum_d[0] + wsum_d[1];
            g_adst[n * 2 + 1] = wsum_d[2] + wsum_d[3];
        }
        __syncthreads();   // protect xs/wsum before next iteration rewrites
    }
}

// ---------------------------------------------------------------------------
// K2: single edge pass. One warp per edge (incl. N self-loops):
//   ex = exp(leakyrelu(a_src[s] + a_dst[d]))  per head
//   denom[d] += ex   (lane 0, scalar REDs)
//   out[d,:] += ex * h[s,:]   (32 lanes x red.global.add.v4.f32)
// Normalization deferred to K3 (divide by denom) — algebraically identical.
// ---------------------------------------------------------------------------
__global__ __launch_bounds__(256) void edge_kernel(
    const int* __restrict__ src,
    const int* __restrict__ dst,
    float* __restrict__ out)
{
    int gw = (blockIdx.x * blockDim.x + threadIdx.x) >> 5;
    int lane = threadIdx.x & 31;
    if (gw >= E_EDGES + N_NODES) return;

    int s, d;
    if (gw < E_EDGES) { s = __ldg(src + gw); d = __ldg(dst + gw); }
    else              { s = d = gw - E_EDGES; }           // self loop

    float2 as = *(const float2*)(g_asrc + (size_t)s * 2);
    float2 ad = *(const float2*)(g_adst + (size_t)d * 2);
    float e0 = as.x + ad.x; e0 = (e0 > 0.0f) ? e0 : NEG_SLOPE * e0;
    float e1 = as.y + ad.y; e1 = (e1 > 0.0f) ? e1 : NEG_SLOPE * e1;
    float ex0 = __expf(e0);
    float ex1 = __expf(e1);

    if (lane == 0) {
        atomicAdd(g_denom + (size_t)d * 2 + 0, ex0);
        atomicAdd(g_denom + (size_t)d * 2 + 1, ex1);
    }

    float ex = (lane < 16) ? ex0 : ex1;   // lanes 0-15: head0, 16-31: head1
    float4 v = *(const float4*)(g_h + (size_t)s * HC + lane * 4);
    float4 r = make_float4(v.x * ex, v.y * ex, v.z * ex, v.w * ex);
    float* p = out + (size_t)d * HC + lane * 4;
    asm volatile("red.global.add.v4.f32 [%0], {%1,%2,%3,%4};"
                 :: "l"(p), "f"(r.x), "f"(r.y), "f"(r.z), "f"(r.w)
                 : "memory");
}

// ---------------------------------------------------------------------------
// K3: normalize + bias:  out[n,j] = out[n,j] / (denom[n,head] + 1e-16) + bias[j]
// ---------------------------------------------------------------------------
__global__ void final_kernel(float* __restrict__ out, const float* __restrict__ bias) {
    int i = blockIdx.x * blockDim.x + threadIdx.x;
    if (i >= N_NODES * HC) return;
    int n = i >> 7;
    int col = i & 127;
    int h = col >> 6;
    out[i] = out[i] / (g_denom[n * 2 + h] + 1e-16f) + bias[col];
}

// ---------------------------------------------------------------------------
// Inputs (metadata order): edge_index[2,E] i32, users_feature, items_feature,
//                          W, att_src, att_dst, bias   — all float32.
// ---------------------------------------------------------------------------
extern "C" void kernel_launch(void* const* d_in, const int* in_sizes, int n_in,
                              void* d_out, int out_size)
{
    const int*   edge_index = (const int*)d_in[0];
    const float* users      = (const float*)d_in[1];
    const float* items      = (const float*)d_in[2];
    const float* W          = (const float*)d_in[3];
    const float* att_src    = (const float*)d_in[4];
    const float* att_dst    = (const float*)d_in[5];
    const float* bias       = (const float*)d_in[6];
    float* out = (float*)d_out;

    const int* src = edge_index;
    const int* dst = edge_index + E_EDGES;

    zero_kernel<<<1024, 256>>>(out);

    int gemm_blocks = (N_NODES + ROWS_PER_BLOCK - 1) / ROWS_PER_BLOCK;
    gemm_kernel<<<gemm_blocks, 128>>>(users, items, W, att_src, att_dst);

    long long total_warps = (long long)E_EDGES + N_NODES;
    long long edge_blocks = (total_warps * 32 + 255) / 256;
    edge_kernel<<<(int)edge_blocks, 256>>>(src, dst, out);

    int fin_blocks = (N_NODES * HC + 255) / 256;
    final_kernel<<<fin_blocks, 256>>>(out, bias);
}

// round 3
// speedup vs baseline: 1.8071x; 1.8071x over previous
#include <cuda_runtime.h>

#define N_USERS 17449
#define N_ITEMS 48676
#define N_NODES (N_USERS + N_ITEMS)   // 66125
#define D_IN    64
#define HC      128                    // H*C = 2*64
#define E_EDGES 2000000
#define NEG_SLOPE 0.2f

// Scratch (no cudaMalloc allowed): ~43 MB of __device__ globals.
__device__ float g_h[(size_t)N_NODES * HC];     // transformed features [N,128]
__device__ float g_asrc[N_NODES * 2];           // per-node src logits [N,H]
__device__ float g_adst[N_NODES * 2];           // per-node dst logits [N,H]
__device__ int   g_deg[N_NODES];                // in-degree (excl. self loop)
__device__ int   g_off[N_NODES + 1];            // CSR offsets
__device__ int   g_cur[N_NODES];                // scatter cursors
__device__ int   g_csr_src[E_EDGES];            // src id per edge, bucketed by dst

// ---------------------------------------------------------------------------
// K0: zero degree counters
// ---------------------------------------------------------------------------
__global__ void init_deg_kernel() {
    int i = blockIdx.x * blockDim.x + threadIdx.x;
    if (i < N_NODES) g_deg[i] = 0;
}

// ---------------------------------------------------------------------------
// K1: h = x @ W  (x = concat(users, items)), fused a_src/a_dst reductions.
// ---------------------------------------------------------------------------
#define ROWS_PER_BLOCK 32

__global__ __launch_bounds__(128) void gemm_kernel(
    const float* __restrict__ users,
    const float* __restrict__ items,
    const float* __restrict__ W,        // [64,128] row-major
    const float* __restrict__ att_src,  // [2,64] flattened = 128
    const float* __restrict__ att_dst)
{
    __shared__ float Ws[D_IN * HC];     // 32 KB
    __shared__ float xs[D_IN];
    __shared__ float wsum_s[4], wsum_d[4];

    int tid = threadIdx.x;              // output column j = head*64 + c
    for (int i = tid; i < D_IN * HC; i += 128) Ws[i] = W[i];
    float as = att_src[tid];
    float ad = att_dst[tid];

    int row0 = blockIdx.x * ROWS_PER_BLOCK;
    __syncthreads();

    for (int rr = 0; rr < ROWS_PER_BLOCK; rr++) {
        int n = row0 + rr;
        if (n >= N_NODES) break;

        if (tid < D_IN) {
            xs[tid] = (n < N_USERS) ? users[(size_t)n * D_IN + tid]
                                    : items[(size_t)(n - N_USERS) * D_IN + tid];
        }
        __syncthreads();

        float acc = 0.0f;
        #pragma unroll
        for (int k = 0; k < D_IN; k++)
            acc = fmaf(xs[k], Ws[k * HC + tid], acc);

        g_h[(size_t)n * HC + tid] = acc;

        float ps = acc * as;
        float pd = acc * ad;
        #pragma unroll
        for (int o = 16; o > 0; o >>= 1) {
            ps += __shfl_down_sync(0xffffffffu, ps, o);
            pd += __shfl_down_sync(0xffffffffu, pd, o);
        }
        int w = tid >> 5;
        if ((tid & 31) == 0) { wsum_s[w] = ps; wsum_d[w] = pd; }
        __syncthreads();
        if (tid == 0) {
            g_asrc[n * 2 + 0] = wsum_s[0] + wsum_s[1];
            g_asrc[n * 2 + 1] = wsum_s[2] + wsum_s[3];
            g_adst[n * 2 + 0] = wsum_d[0] + wsum_d[1];
            g_adst[n * 2 + 1] = wsum_d[2] + wsum_d[3];
        }
        __syncthreads();
    }
}

// ---------------------------------------------------------------------------
// K2: degree histogram over destinations
// ---------------------------------------------------------------------------
__global__ void count_kernel(const int* __restrict__ dst) {
    int e = blockIdx.x * blockDim.x + threadIdx.x;
    if (e < E_EDGES) atomicAdd(&g_deg[dst[e]], 1);
}

// ---------------------------------------------------------------------------
// K3: exclusive prefix sum over 66125 degrees, single block of 1024 threads.
// ---------------------------------------------------------------------------
__global__ __launch_bounds__(1024) void scan_kernel() {
    __shared__ int sums[1024];
    const int CHUNK = (N_NODES + 1023) / 1024;   // 65
    int t = threadIdx.x;
    int base = t * CHUNK;

    int s = 0;
    for (int i = 0; i < CHUNK; i++) {
        int idx = base + i;
        if (idx < N_NODES) s += g_deg[idx];
    }
    sums[t] = s;
    __syncthreads();

    for (int off = 1; off < 1024; off <<= 1) {
        int v = (t >= off) ? sums[t - off] : 0;
        __syncthreads();
        sums[t] += v;
        __syncthreads();
    }

    int run = (t == 0) ? 0 : sums[t - 1];
    for (int i = 0; i < CHUNK; i++) {
        int idx = base + i;
        if (idx < N_NODES) {
            g_off[idx] = run;
            g_cur[idx] = run;
            run += g_deg[idx];
        }
    }
    if (t == 1023) g_off[N_NODES] = sums[1023];   // == E_EDGES
}

// ---------------------------------------------------------------------------
// K4: scatter src ids into dst buckets
// ---------------------------------------------------------------------------
__global__ void scatter_kernel(const int* __restrict__ src,
                               const int* __restrict__ dst) {
    int e = blockIdx.x * blockDim.x + threadIdx.x;
    if (e >= E_EDGES) return;
    int d = dst[e];
    int pos = atomicAdd(&g_cur[d], 1);
    g_csr_src[pos] = src[e];
}

// ---------------------------------------------------------------------------
// K5: per-node gather. One warp per destination node.
// Lanes 0-15 carry head 0 (cols 0-63), lanes 16-31 head 1 (cols 64-127).
// FIX vs R2: shuffle ex0/ex1 separately; select by the RECEIVING lane's head
// (previous version broadcast lane k's head-dependent pick — wrong).
// ---------------------------------------------------------------------------
__global__ __launch_bounds__(256) void gather_kernel(
    float* __restrict__ out,
    const float* __restrict__ bias)
{
    int node = blockIdx.x * 8 + (threadIdx.x >> 5);
    if (node >= N_NODES) return;
    int lane = threadIdx.x & 31;
    int head = lane >> 4;

    float2 ad2 = *(const float2*)(g_adst + (size_t)node * 2);
    float2 a2  = *(const float2*)(g_asrc + (size_t)node * 2);

    // self loop
    float es = (head ? a2.y : a2.x) + (head ? ad2.y : ad2.x);
    es = (es > 0.0f) ? es : NEG_SLOPE * es;
    float exs = __expf(es);
    float4 v0 = *(const float4*)(g_h + (size_t)node * HC + lane * 4);
    float4 acc = make_float4(v0.x * exs, v0.y * exs, v0.z * exs, v0.w * exs);
    float den = exs;

    int start = g_off[node];
    int end   = g_off[node + 1];

    for (int j0 = start; j0 < end; j0 += 32) {
        int myj = j0 + lane;
        int s = 0;
        float ex0 = 0.0f, ex1 = 0.0f;
        if (myj < end) {
            s = g_csr_src[myj];
            float2 a = *(const float2*)(g_asrc + (size_t)s * 2);
            float e0 = a.x + ad2.x; e0 = (e0 > 0.0f) ? e0 : NEG_SLOPE * e0;
            float e1 = a.y + ad2.y; e1 = (e1 > 0.0f) ? e1 : NEG_SLOPE * e1;
            ex0 = __expf(e0);
            ex1 = __expf(e1);
        }
        int cnt = min(32, end - j0);
        #pragma unroll 4
        for (int k = 0; k < cnt; k++) {
            int   sk  = __shfl_sync(0xffffffffu, s,   k);
            float e0k = __shfl_sync(0xffffffffu, ex0, k);
            float e1k = __shfl_sync(0xffffffffu, ex1, k);
            float exh = head ? e1k : e0k;
            float4 vv = *(const float4*)(g_h + (size_t)sk * HC + lane * 4);
            acc.x = fmaf(exh, vv.x, acc.x);
            acc.y = fmaf(exh, vv.y, acc.y);
            acc.z = fmaf(exh, vv.z, acc.z);
            acc.w = fmaf(exh, vv.w, acc.w);
            den += exh;
        }
    }

    float inv = 1.0f / (den + 1e-16f);
    float4 b = *(const float4*)(bias + lane * 4);
    float4 o = make_float4(acc.x * inv + b.x, acc.y * inv + b.y,
                           acc.z * inv + b.z, acc.w * inv + b.w);
    *(float4*)(out + (size_t)node * HC + lane * 4) = o;
}

// ---------------------------------------------------------------------------
// Inputs (metadata order): edge_index[2,E] i32, users_feature, items_feature,
//                          W, att_src, att_dst, bias   — all float32.
// ---------------------------------------------------------------------------
extern "C" void kernel_launch(void* const* d_in, const int* in_sizes, int n_in,
                              void* d_out, int out_size)
{
    const int*   edge_index = (const int*)d_in[0];
    const float* users      = (const float*)d_in[1];
    const float* items      = (const float*)d_in[2];
    const float* W          = (const float*)d_in[3];
    const float* att_src    = (const float*)d_in[4];
    const float* att_dst    = (const float*)d_in[5];
    const float* bias       = (const float*)d_in[6];
    float* out = (float*)d_out;

    const int* src = edge_index;
    const int* dst = edge_index + E_EDGES;

    init_deg_kernel<<<(N_NODES + 255) / 256, 256>>>();

    int gemm_blocks = (N_NODES + ROWS_PER_BLOCK - 1) / ROWS_PER_BLOCK;
    gemm_kernel<<<gemm_blocks, 128>>>(users, items, W, att_src, att_dst);

    int eblocks = (E_EDGES + 255) / 256;
    count_kernel<<<eblocks, 256>>>(dst);
    scan_kernel<<<1, 1024>>>();
    scatter_kernel<<<eblocks, 256>>>(src, dst);

    int gblocks = (N_NODES + 7) / 8;   // 8 warps per block, 1 node per warp
    gather_kernel<<<gblocks, 256>>>(out, bias);
}

// round 5
// speedup vs baseline: 2.5301x; 1.4001x over previous
#include <cuda_runtime.h>
#include <cuda_fp16.h>

#define N_USERS 17449
#define N_ITEMS 48676
#define N_NODES (N_USERS + N_ITEMS)   // 66125
#define D_IN    64
#define HC      128                    // H*C = 2*64
#define E_EDGES 2000000
#define NEG_SLOPE 0.2f
#define SCAN_BLK 1024
#define NSCAN_BLOCKS ((N_NODES + SCAN_BLK - 1) / SCAN_BLK)   // 65

// Scratch (no cudaMalloc allowed): ~26 MB of __device__ globals.
__device__ __half g_h[(size_t)N_NODES * HC];    // transformed features [N,128], fp16
__device__ float g_asrc[N_NODES * 2];           // per-node src logits [N,H]
__device__ float g_adst[N_NODES * 2];           // per-node dst logits [N,H]
__device__ int   g_deg[N_NODES];                // in-degree (excl. self loop)
__device__ int   g_off[N_NODES + 1];            // CSR offsets
__device__ int   g_cur[N_NODES];                // scatter cursors
__device__ int   g_bsum[NSCAN_BLOCKS];          // per-block degree sums
__device__ int   g_boff[NSCAN_BLOCKS];          // scanned block offsets
__device__ int   g_csr_src[E_EDGES];            // src id per edge, bucketed by dst

// ---------------------------------------------------------------------------
// K0: zero degree counters
// ---------------------------------------------------------------------------
__global__ void init_deg_kernel() {
    int i = blockIdx.x * blockDim.x + threadIdx.x;
    if (i < N_NODES) g_deg[i] = 0;
}

// ---------------------------------------------------------------------------
// K1: h = x @ W, fused a_src/a_dst reductions. h stored fp16 (logits fp32).
// ---------------------------------------------------------------------------
#define ROWS_PER_BLOCK 32

__global__ __launch_bounds__(128) void gemm_kernel(
    const float* __restrict__ users,
    const float* __restrict__ items,
    const float* __restrict__ W,        // [64,128] row-major
    const float* __restrict__ att_src,  // [2,64] flattened = 128
    const float* __restrict__ att_dst)
{
    __shared__ float Ws[D_IN * HC];     // 32 KB
    __shared__ float xs[D_IN];
    __shared__ float wsum_s[4], wsum_d[4];

    int tid = threadIdx.x;              // output column j = head*64 + c
    for (int i = tid; i < D_IN * HC; i += 128) Ws[i] = W[i];
    float as = att_src[tid];
    float ad = att_dst[tid];

    int row0 = blockIdx.x * ROWS_PER_BLOCK;
    __syncthreads();

    for (int rr = 0; rr < ROWS_PER_BLOCK; rr++) {
        int n = row0 + rr;
        if (n >= N_NODES) break;

        if (tid < D_IN) {
            xs[tid] = (n < N_USERS) ? users[(size_t)n * D_IN + tid]
                                    : items[(size_t)(n - N_USERS) * D_IN + tid];
        }
        __syncthreads();

        float acc = 0.0f;
        #pragma unroll
        for (int k = 0; k < D_IN; k++)
            acc = fmaf(xs[k], Ws[k * HC + tid], acc);

        g_h[(size_t)n * HC + tid] = __float2half_rn(acc);

        float ps = acc * as;
        float pd = acc * ad;
        #pragma unroll
        for (int o = 16; o > 0; o >>= 1) {
            ps += __shfl_down_sync(0xffffffffu, ps, o);
            pd += __shfl_down_sync(0xffffffffu, pd, o);
        }
        int w = tid >> 5;
        if ((tid & 31) == 0) { wsum_s[w] = ps; wsum_d[w] = pd; }
        __syncthreads();
        if (tid == 0) {
            g_asrc[n * 2 + 0] = wsum_s[0] + wsum_s[1];
            g_asrc[n * 2 + 1] = wsum_s[2] + wsum_s[3];
            g_adst[n * 2 + 0] = wsum_d[0] + wsum_d[1];
            g_adst[n * 2 + 1] = wsum_d[2] + wsum_d[3];
        }
        __syncthreads();
    }
}

// ---------------------------------------------------------------------------
// K2: degree histogram over destinations
// ---------------------------------------------------------------------------
__global__ void count_kernel(const int* __restrict__ dst) {
    int e = blockIdx.x * blockDim.x + threadIdx.x;
    if (e < E_EDGES) atomicAdd(&g_deg[dst[e]], 1);
}

// ---------------------------------------------------------------------------
// K3a: per-block exclusive scan (shfl-based), block sums to g_bsum.
// ---------------------------------------------------------------------------
__global__ __launch_bounds__(SCAN_BLK) void scan1_kernel() {
    __shared__ int wsums[32];
    int t = threadIdx.x;
    int i = blockIdx.x * SCAN_BLK + t;
    int d = (i < N_NODES) ? g_deg[i] : 0;

    int lane = t & 31, warp = t >> 5;
    int incl = d;
    #pragma unroll
    for (int o = 1; o < 32; o <<= 1) {
        int v = __shfl_up_sync(0xffffffffu, incl, o);
        if (lane >= o) incl += v;
    }
    if (lane == 31) wsums[warp] = incl;
    __syncthreads();
    if (warp == 0) {
        int v = (lane < 32) ? wsums[lane] : 0;
        #pragma unroll
        for (int o = 1; o < 32; o <<= 1) {
            int u = __shfl_up_sync(0xffffffffu, v, o);
            if (lane >= o) v += u;
        }
        wsums[lane] = v;
    }
    __syncthreads();
    int base = (warp > 0) ? wsums[warp - 1] : 0;
    incl += base;
    if (i < N_NODES) g_off[i] = incl - d;   // block-local exclusive
    if (t == SCAN_BLK - 1) g_bsum[blockIdx.x] = incl;
}

// ---------------------------------------------------------------------------
// K3b: scan the 65 block sums (tiny single block)
// ---------------------------------------------------------------------------
__global__ __launch_bounds__(128) void scan2_kernel() {
    __shared__ int s[128];
    int t = threadIdx.x;
    s[t] = (t < NSCAN_BLOCKS) ? g_bsum[t] : 0;
    __syncthreads();
    for (int o = 1; o < 128; o <<= 1) {
        int v = (t >= o) ? s[t - o] : 0;
        __syncthreads();
        s[t] += v;
        __syncthreads();
    }
    if (t < NSCAN_BLOCKS) g_boff[t] = (t == 0) ? 0 : s[t - 1];
    if (t == 0) g_off[N_NODES] = E_EDGES;
}

// ---------------------------------------------------------------------------
// K3c: add block offsets, init cursors
// ---------------------------------------------------------------------------
__global__ __launch_bounds__(SCAN_BLK) void scan3_kernel() {
    int i = blockIdx.x * SCAN_BLK + threadIdx.x;
    if (i < N_NODES) {
        int v = g_off[i] + g_boff[blockIdx.x];
        g_off[i] = v;
        g_cur[i] = v;
    }
}

// ---------------------------------------------------------------------------
// K4: scatter src ids into dst buckets
// ---------------------------------------------------------------------------
__global__ void scatter_kernel(const int* __restrict__ src,
                               const int* __restrict__ dst) {
    int e = blockIdx.x * blockDim.x + threadIdx.x;
    if (e >= E_EDGES) return;
    int d = dst[e];
    int pos = atomicAdd(&g_cur[d], 1);
    g_csr_src[pos] = src[e];
}

// ---------------------------------------------------------------------------
// K5: per-node gather. One warp per destination node. h rows are fp16 (8 B
// per lane per edge). Logits/exp/accumulation in fp32.
// Lanes 0-15 carry head 0 (cols 0-63), lanes 16-31 head 1 (cols 64-127).
// ---------------------------------------------------------------------------
__global__ __launch_bounds__(256) void gather_kernel(
    float* __restrict__ out,
    const float* __restrict__ bias)
{
    int node = blockIdx.x * 8 + (threadIdx.x >> 5);
    if (node >= N_NODES) return;
    int lane = threadIdx.x & 31;
    int head = lane >> 4;

    float2 ad2 = *(const float2*)(g_adst + (size_t)node * 2);
    float2 a2  = *(const float2*)(g_asrc + (size_t)node * 2);

    // self loop
    float es = (head ? a2.y : a2.x) + (head ? ad2.y : ad2.x);
    es = (es > 0.0f) ? es : NEG_SLOPE * es;
    float exs = __expf(es);
    uint2 raw0 = *(const uint2*)(g_h + (size_t)node * HC + lane * 4);
    __half2 p0 = *reinterpret_cast<__half2*>(&raw0.x);
    __half2 p1 = *reinterpret_cast<__half2*>(&raw0.y);
    float2 f0 = __half22float2(p0), f1 = __half22float2(p1);
    float4 acc = make_float4(f0.x * exs, f0.y * exs, f1.x * exs, f1.y * exs);
    float den = exs;

    int start = g_off[node];
    int end   = g_off[node + 1];

    for (int j0 = start; j0 < end; j0 += 32) {
        int myj = j0 + lane;
        int s = 0;
        float ex0 = 0.0f, ex1 = 0.0f;
        if (myj < end) {
            s = g_csr_src[myj];
            float2 a = *(const float2*)(g_asrc + (size_t)s * 2);
            float e0 = a.x + ad2.x; e0 = (e0 > 0.0f) ? e0 : NEG_SLOPE * e0;
            float e1 = a.y + ad2.y; e1 = (e1 > 0.0f) ? e1 : NEG_SLOPE * e1;
            ex0 = __expf(e0);
            ex1 = __expf(e1);
        }
        int cnt = min(32, end - j0);
        #pragma unroll 4
        for (int k = 0; k < cnt; k++) {
            int   sk  = __shfl_sync(0xffffffffu, s,   k);
            float e0k = __shfl_sync(0xffffffffu, ex0, k);
            float e1k = __shfl_sync(0xffffffffu, ex1, k);
            float exh = head ? e1k : e0k;
            uint2 raw = *(const uint2*)(g_h + (size_t)sk * HC + lane * 4);
            __half2 q0 = *reinterpret_cast<__half2*>(&raw.x);
            __half2 q1 = *reinterpret_cast<__half2*>(&raw.y);
            float2 g0 = __half22float2(q0), g1 = __half22float2(q1);
            acc.x = fmaf(exh, g0.x, acc.x);
            acc.y = fmaf(exh, g0.y, acc.y);
            acc.z = fmaf(exh, g1.x, acc.z);
            acc.w = fmaf(exh, g1.y, acc.w);
            den += exh;
        }
    }

    float inv = 1.0f / (den + 1e-16f);
    float4 b = *(const float4*)(bias + lane * 4);
    float4 o = make_float4(acc.x * inv + b.x, acc.y * inv + b.y,
                           acc.z * inv + b.z, acc.w * inv + b.w);
    *(float4*)(out + (size_t)node * HC + lane * 4) = o;
}

// ---------------------------------------------------------------------------
// Inputs (metadata order): edge_index[2,E] i32, users_feature, items_feature,
//                          W, att_src, att_dst, bias   — all float32.
// ---------------------------------------------------------------------------
extern "C" void kernel_launch(void* const* d_in, const int* in_sizes, int n_in,
                              void* d_out, int out_size)
{
    const int*   edge_index = (const int*)d_in[0];
    const float* users      = (const float*)d_in[1];
    const float* items      = (const float*)d_in[2];
    const float* W          = (const float*)d_in[3];
    const float* att_src    = (const float*)d_in[4];
    const float* att_dst    = (const float*)d_in[5];
    const float* bias       = (const float*)d_in[6];
    float* out = (float*)d_out;

    const int* src = edge_index;
    const int* dst = edge_index + E_EDGES;

    init_deg_kernel<<<(N_NODES + 255) / 256, 256>>>();

    int gemm_blocks = (N_NODES + ROWS_PER_BLOCK - 1) / ROWS_PER_BLOCK;
    gemm_kernel<<<gemm_blocks, 128>>>(users, items, W, att_src, att_dst);

    int eblocks = (E_EDGES + 255) / 256;
    count_kernel<<<eblocks, 256>>>(dst);

    scan1_kernel<<<NSCAN_BLOCKS, SCAN_BLK>>>();
    scan2_kernel<<<1, 128>>>();
    scan3_kernel<<<NSCAN_BLOCKS, SCAN_BLK>>>();

    scatter_kernel<<<eblocks, 256>>>(src, dst);

    int gblocks = (N_NODES + 7) / 8;   // 8 warps per block, 1 node per warp
    gather_kernel<<<gblocks, 256>>>(out, bias);
}

// round 6
// speedup vs baseline: 2.6502x; 1.0475x over previous
#include <cuda_runtime.h>
#include <cuda_fp16.h>

#define N_USERS 17449
#define N_ITEMS 48676
#define N_NODES (N_USERS + N_ITEMS)   // 66125
#define D_IN    64
#define HC      128                    // H*C = 2*64
#define E_EDGES 2000000
#define NEG_SLOPE 0.2f
#define SCAN_BLK 1024
#define NSCAN_BLOCKS ((N_NODES + SCAN_BLK - 1) / SCAN_BLK)   // 65

#define ROWS_PER_BLOCK 32
#define GEMM_BLOCKS ((N_NODES + ROWS_PER_BLOCK - 1) / ROWS_PER_BLOCK)  // 2067
#define COUNT_BLOCKS 8192

// Scratch (no cudaMalloc allowed): ~26 MB of __device__ globals.
// NOTE: g_deg relies on zero-init at module load for the first run; scan1
// re-zeroes it after reading, keeping every graph replay deterministic.
__device__ __half g_h[(size_t)N_NODES * HC];    // transformed features [N,128], fp16
__device__ float g_asrc[N_NODES * 2];           // per-node src logits [N,H]
__device__ float g_adst[N_NODES * 2];           // per-node dst logits [N,H]
__device__ int   g_deg[N_NODES];                // in-degree (excl. self loop)
__device__ int   g_off[N_NODES + 1];            // CSR offsets
__device__ int   g_cur[N_NODES];                // scatter cursors
__device__ int   g_bsum[NSCAN_BLOCKS];          // per-block degree sums
__device__ int   g_boff[NSCAN_BLOCKS];          // scanned block offsets
__device__ int   g_csr_src[E_EDGES];            // src id per edge, bucketed by dst

// ---------------------------------------------------------------------------
// K1: fused  (a) h = x @ W + logit reductions   (b) degree histogram.
// Blocks [0, GEMM_BLOCKS) do the gemm; blocks above do grid-stride count.
// Independent outputs -> safe to overlap in one launch.
// ---------------------------------------------------------------------------
__global__ __launch_bounds__(128) void gemm_count_kernel(
    const float* __restrict__ users,
    const float* __restrict__ items,
    const float* __restrict__ W,        // [64,128] row-major
    const float* __restrict__ att_src,  // [2,64] flattened = 128
    const float* __restrict__ att_dst,
    const int* __restrict__ dst)
{
    __shared__ float Ws[D_IN * HC];     // 32 KB
    __shared__ float xs[D_IN];
    __shared__ float wsum_s[4], wsum_d[4];

    if (blockIdx.x >= GEMM_BLOCKS) {
        // ---- degree histogram part ----
        int b = blockIdx.x - GEMM_BLOCKS;
        int stride = COUNT_BLOCKS * 128;
        for (int e = b * 128 + threadIdx.x; e < E_EDGES; e += stride)
            atomicAdd(&g_deg[dst[e]], 1);
        return;
    }

    // ---- gemm part ----
    int tid = threadIdx.x;              // output column j = head*64 + c
    for (int i = tid; i < D_IN * HC; i += 128) Ws[i] = W[i];
    float as = att_src[tid];
    float ad = att_dst[tid];

    int row0 = blockIdx.x * ROWS_PER_BLOCK;
    __syncthreads();

    for (int rr = 0; rr < ROWS_PER_BLOCK; rr++) {
        int n = row0 + rr;
        if (n >= N_NODES) break;

        if (tid < D_IN) {
            xs[tid] = (n < N_USERS) ? users[(size_t)n * D_IN + tid]
                                    : items[(size_t)(n - N_USERS) * D_IN + tid];
        }
        __syncthreads();

        float acc = 0.0f;
        #pragma unroll
        for (int k = 0; k < D_IN; k++)
            acc = fmaf(xs[k], Ws[k * HC + tid], acc);

        g_h[(size_t)n * HC + tid] = __float2half_rn(acc);

        float ps = acc * as;
        float pd = acc * ad;
        #pragma unroll
        for (int o = 16; o > 0; o >>= 1) {
            ps += __shfl_down_sync(0xffffffffu, ps, o);
            pd += __shfl_down_sync(0xffffffffu, pd, o);
        }
        int w = tid >> 5;
        if ((tid & 31) == 0) { wsum_s[w] = ps; wsum_d[w] = pd; }
        __syncthreads();
        if (tid == 0) {
            g_asrc[n * 2 + 0] = wsum_s[0] + wsum_s[1];
            g_asrc[n * 2 + 1] = wsum_s[2] + wsum_s[3];
            g_adst[n * 2 + 0] = wsum_d[0] + wsum_d[1];
            g_adst[n * 2 + 1] = wsum_d[2] + wsum_d[3];
        }
        __syncthreads();
    }
}

// ---------------------------------------------------------------------------
// K3a: per-block exclusive scan; also RE-ZEROES g_deg for the next replay.
// ---------------------------------------------------------------------------
__global__ __launch_bounds__(SCAN_BLK) void scan1_kernel() {
    __shared__ int wsums[32];
    int t = threadIdx.x;
    int i = blockIdx.x * SCAN_BLK + t;
    int d = (i < N_NODES) ? g_deg[i] : 0;
    if (i < N_NODES) g_deg[i] = 0;      // reset for next graph replay

    int lane = t & 31, warp = t >> 5;
    int incl = d;
    #pragma unroll
    for (int o = 1; o < 32; o <<= 1) {
        int v = __shfl_up_sync(0xffffffffu, incl, o);
        if (lane >= o) incl += v;
    }
    if (lane == 31) wsums[warp] = incl;
    __syncthreads();
    if (warp == 0) {
        int v = (lane < 32) ? wsums[lane] : 0;
        #pragma unroll
        for (int o = 1; o < 32; o <<= 1) {
            int u = __shfl_up_sync(0xffffffffu, v, o);
            if (lane >= o) v += u;
        }
        wsums[lane] = v;
    }
    __syncthreads();
    int base = (warp > 0) ? wsums[warp - 1] : 0;
    incl += base;
    if (i < N_NODES) g_off[i] = incl - d;   // block-local exclusive
    if (t == SCAN_BLK - 1) g_bsum[blockIdx.x] = incl;
}

// ---------------------------------------------------------------------------
// K3b: scan the 65 block sums (tiny single block)
// ---------------------------------------------------------------------------
__global__ __launch_bounds__(128) void scan2_kernel() {
    __shared__ int s[128];
    int t = threadIdx.x;
    s[t] = (t < NSCAN_BLOCKS) ? g_bsum[t] : 0;
    __syncthreads();
    for (int o = 1; o < 128; o <<= 1) {
        int v = (t >= o) ? s[t - o] : 0;
        __syncthreads();
        s[t] += v;
        __syncthreads();
    }
    if (t < NSCAN_BLOCKS) g_boff[t] = (t == 0) ? 0 : s[t - 1];
    if (t == 0) g_off[N_NODES] = E_EDGES;
}

// ---------------------------------------------------------------------------
// K3c: add block offsets, init cursors
// ---------------------------------------------------------------------------
__global__ __launch_bounds__(SCAN_BLK) void scan3_kernel() {
    int i = blockIdx.x * SCAN_BLK + threadIdx.x;
    if (i < N_NODES) {
        int v = g_off[i] + g_boff[blockIdx.x];
        g_off[i] = v;
        g_cur[i] = v;
    }
}

// ---------------------------------------------------------------------------
// K4: scatter src ids into dst buckets
// ---------------------------------------------------------------------------
__global__ void scatter_kernel(const int* __restrict__ src,
                               const int* __restrict__ dst) {
    int e = blockIdx.x * blockDim.x + threadIdx.x;
    if (e >= E_EDGES) return;
    int d = dst[e];
    int pos = atomicAdd(&g_cur[d], 1);
    g_csr_src[pos] = src[e];
}

// ---------------------------------------------------------------------------
// K5: per-node gather. One warp per destination node.
// Lane-parallel phase computes (ex0, ex1, src) per edge + per-lane den sums,
// stages the batch in smem; serial phase reads them via broadcast LDS.128
// (address linear in k -> hoistable, unlike shuffles) + LDG.64 fp16 h row.
// Lanes 0-15 carry head 0 (cols 0-63), lanes 16-31 head 1 (cols 64-127).
// ---------------------------------------------------------------------------
__global__ __launch_bounds__(256) void gather_kernel(
    float* __restrict__ out,
    const float* __restrict__ bias)
{
    __shared__ float4 stage[8][32];     // 4 KB: per warp, 32 edges x 16 B

    int wid_in_blk = threadIdx.x >> 5;
    int node = blockIdx.x * 8 + wid_in_blk;
    if (node >= N_NODES) return;
    int lane = threadIdx.x & 31;
    int head = lane >> 4;

    float2 ad2 = *(const float2*)(g_adst + (size_t)node * 2);
    float2 a2  = *(const float2*)(g_asrc + (size_t)node * 2);

    // self loop (both heads explicitly; acc uses this lane's head)
    float e0s = a2.x + ad2.x; e0s = (e0s > 0.0f) ? e0s : NEG_SLOPE * e0s;
    float e1s = a2.y + ad2.y; e1s = (e1s > 0.0f) ? e1s : NEG_SLOPE * e1s;
    float exs0 = __expf(e0s);
    float exs1 = __expf(e1s);
    float exsh = head ? exs1 : exs0;

    uint2 raw0 = *(const uint2*)(g_h + (size_t)node * HC + lane * 4);
    __half2 p0 = *reinterpret_cast<__half2*>(&raw0.x);
    __half2 p1 = *reinterpret_cast<__half2*>(&raw0.y);
    float2 f0 = __half22float2(p0), f1 = __half22float2(p1);
    float4 acc = make_float4(f0.x * exsh, f0.y * exsh, f1.x * exsh, f1.y * exsh);

    float dsum0 = 0.0f, dsum1 = 0.0f;   // per-lane partial denominators

    int start = g_off[node];
    int end   = g_off[node + 1];

    for (int j0 = start; j0 < end; j0 += 32) {
        int myj = j0 + lane;
        float ex0 = 0.0f, ex1 = 0.0f;
        int s = 0;
        if (myj < end) {
            s = g_csr_src[myj];
            float2 a = *(const float2*)(g_asrc + (size_t)s * 2);
            float e0 = a.x + ad2.x; e0 = (e0 > 0.0f) ? e0 : NEG_SLOPE * e0;
            float e1 = a.y + ad2.y; e1 = (e1 > 0.0f) ? e1 : NEG_SLOPE * e1;
            ex0 = __expf(e0);
            ex1 = __expf(e1);
        }
        dsum0 += ex0;
        dsum1 += ex1;
        stage[wid_in_blk][lane] = make_float4(ex0, ex1, __int_as_float(s), 0.0f);
        __syncwarp();

        int cnt = min(32, end - j0);
        #pragma unroll 4
        for (int k = 0; k < cnt; k++) {
            float4 t = stage[wid_in_blk][k];         // broadcast LDS.128
            float exh = head ? t.y : t.x;
            int   sk  = __float_as_int(t.z);
            uint2 raw = *(const uint2*)(g_h + (size_t)sk * HC + lane * 4);
            __half2 q0 = *reinterpret_cast<__half2*>(&raw.x);
            __half2 q1 = *reinterpret_cast<__half2*>(&raw.y);
            float2 g0 = __half22float2(q0), g1 = __half22float2(q1);
            acc.x = fmaf(exh, g0.x, acc.x);
            acc.y = fmaf(exh, g0.y, acc.y);
            acc.z = fmaf(exh, g1.x, acc.z);
            acc.w = fmaf(exh, g1.y, acc.w);
        }
        __syncwarp();   // before next batch overwrites stage
    }

    // reduce per-lane denominator partials across the warp
    #pragma unroll
    for (int o = 16; o > 0; o >>= 1) {
        dsum0 += __shfl_xor_sync(0xffffffffu, dsum0, o);
        dsum1 += __shfl_xor_sync(0xffffffffu, dsum1, o);
    }
    float den = (head ? (dsum1 + exs1) : (dsum0 + exs0));

    float inv = 1.0f / (den + 1e-16f);
    float4 b = *(const float4*)(bias + lane * 4);
    float4 o = make_float4(acc.x * inv + b.x, acc.y * inv + b.y,
                           acc.z * inv + b.z, acc.w * inv + b.w);
    *(float4*)(out + (size_t)node * HC + lane * 4) = o;
}

// ---------------------------------------------------------------------------
// Inputs (metadata order): edge_index[2,E] i32, users_feature, items_feature,
//                          W, att_src, att_dst, bias   — all float32.
// ---------------------------------------------------------------------------
extern "C" void kernel_launch(void* const* d_in, const int* in_sizes, int n_in,
                              void* d_out, int out_size)
{
    const int*   edge_index = (const int*)d_in[0];
    const float* users      = (const float*)d_in[1];
    const float* items      = (const float*)d_in[2];
    const float* W          = (const float*)d_in[3];
    const float* att_src    = (const float*)d_in[4];
    const float* att_dst    = (const float*)d_in[5];
    const float* bias       = (const float*)d_in[6];
    float* out = (float*)d_out;

    const int* src = edge_index;
    const int* dst = edge_index + E_EDGES;

    gemm_count_kernel<<<GEMM_BLOCKS + COUNT_BLOCKS, 128>>>(
        users, items, W, att_src, att_dst, dst);

    scan1_kernel<<<NSCAN_BLOCKS, SCAN_BLK>>>();
    scan2_kernel<<<1, 128>>>();
    scan3_kernel<<<NSCAN_BLOCKS, SCAN_BLK>>>();

    int eblocks = (E_EDGES + 255) / 256;
    scatter_kernel<<<eblocks, 256>>>(src, dst);

    int gblocks = (N_NODES + 7) / 8;   // 8 warps per block, 1 node per warp
    gather_kernel<<<gblocks, 256>>>(out, bias);
}

// round 9
// speedup vs baseline: 2.6961x; 1.0173x over previous
#include <cuda_runtime.h>
#include <cuda_fp16.h>

#define N_USERS 17449
#define N_ITEMS 48676
#define N_NODES (N_USERS + N_ITEMS)   // 66125
#define D_IN    64
#define HC      128                    // H*C = 2*64
#define E_EDGES 2000000
#define NEG_SLOPE 0.2f
#define SCAN_BLK 1024
#define NSCAN_BLOCKS ((N_NODES + SCAN_BLK - 1) / SCAN_BLK)   // 65

#define ROWS_PER_BLOCK 32
#define GEMM_BLOCKS ((N_NODES + ROWS_PER_BLOCK - 1) / ROWS_PER_BLOCK)  // 2067
#define COUNT_BLOCKS 8192

// Scratch (no cudaMalloc allowed): ~26 MB of __device__ globals.
// g_deg is zero-initialized at load; scan1 re-zeroes after reading so every
// graph replay is deterministic.
__device__ __half g_h[(size_t)N_NODES * HC];    // transformed features [N,128], fp16
__device__ float g_asrc[N_NODES * 2];           // per-node src logits [N,H]
__device__ float g_adst[N_NODES * 2];           // per-node dst logits [N,H]
__device__ int   g_deg[N_NODES];                // in-degree (excl. self loop)
__device__ int   g_off[N_NODES + 1];            // CSR offsets
__device__ int   g_cur[N_NODES];                // scatter cursors
__device__ int   g_bsum[NSCAN_BLOCKS];          // per-block degree sums
__device__ int   g_boff[NSCAN_BLOCKS];          // scanned block offsets
__device__ int   g_csr_src[E_EDGES];            // src id per edge, bucketed by dst

// ---------------------------------------------------------------------------
// K1: fused  (a) h = x @ W + logit reductions   (b) degree histogram.
// ---------------------------------------------------------------------------
__global__ __launch_bounds__(128) void gemm_count_kernel(
    const float* __restrict__ users,
    const float* __restrict__ items,
    const float* __restrict__ W,        // [64,128] row-major
    const float* __restrict__ att_src,  // [2,64] flattened = 128
    const float* __restrict__ att_dst,
    const int* __restrict__ dst)
{
    __shared__ float Ws[D_IN * HC];     // 32 KB
    __shared__ float xs[D_IN];
    __shared__ float wsum_s[4], wsum_d[4];

    if (blockIdx.x >= GEMM_BLOCKS) {
        int b = blockIdx.x - GEMM_BLOCKS;
        int stride = COUNT_BLOCKS * 128;
        for (int e = b * 128 + threadIdx.x; e < E_EDGES; e += stride)
            atomicAdd(&g_deg[dst[e]], 1);
        return;
    }

    int tid = threadIdx.x;              // output column j = head*64 + c
    for (int i = tid; i < D_IN * HC; i += 128) Ws[i] = W[i];
    float as = att_src[tid];
    float ad = att_dst[tid];

    int row0 = blockIdx.x * ROWS_PER_BLOCK;
    __syncthreads();

    for (int rr = 0; rr < ROWS_PER_BLOCK; rr++) {
        int n = row0 + rr;
        if (n >= N_NODES) break;

        if (tid < D_IN) {
            xs[tid] = (n < N_USERS) ? users[(size_t)n * D_IN + tid]
                                    : items[(size_t)(n - N_USERS) * D_IN + tid];
        }
        __syncthreads();

        float acc = 0.0f;
        #pragma unroll
        for (int k = 0; k < D_IN; k++)
            acc = fmaf(xs[k], Ws[k * HC + tid], acc);

        g_h[(size_t)n * HC + tid] = __float2half_rn(acc);

        float ps = acc * as;
        float pd = acc * ad;
        #pragma unroll
        for (int o = 16; o > 0; o >>= 1) {
            ps += __shfl_down_sync(0xffffffffu, ps, o);
            pd += __shfl_down_sync(0xffffffffu, pd, o);
        }
        int w = tid >> 5;
        if ((tid & 31) == 0) { wsum_s[w] = ps; wsum_d[w] = pd; }
        __syncthreads();
        if (tid == 0) {
            g_asrc[n * 2 + 0] = wsum_s[0] + wsum_s[1];
            g_asrc[n * 2 + 1] = wsum_s[2] + wsum_s[3];
            g_adst[n * 2 + 0] = wsum_d[0] + wsum_d[1];
            g_adst[n * 2 + 1] = wsum_d[2] + wsum_d[3];
        }
        __syncthreads();
    }
}

// ---------------------------------------------------------------------------
// K3a: per-block exclusive scan; also re-zeroes g_deg for the next replay.
// ---------------------------------------------------------------------------
__global__ __launch_bounds__(SCAN_BLK) void scan1_kernel() {
    __shared__ int wsums[32];
    int t = threadIdx.x;
    int i = blockIdx.x * SCAN_BLK + t;
    int d = (i < N_NODES) ? g_deg[i] : 0;
    if (i < N_NODES) g_deg[i] = 0;

    int lane = t & 31, warp = t >> 5;
    int incl = d;
    #pragma unroll
    for (int o = 1; o < 32; o <<= 1) {
        int v = __shfl_up_sync(0xffffffffu, incl, o);
        if (lane >= o) incl += v;
    }
    if (lane == 31) wsums[warp] = incl;
    __syncthreads();
    if (warp == 0) {
        int v = (lane < 32) ? wsums[lane] : 0;
        #pragma unroll
        for (int o = 1; o < 32; o <<= 1) {
            int u = __shfl_up_sync(0xffffffffu, v, o);
            if (lane >= o) v += u;
        }
        wsums[lane] = v;
    }
    __syncthreads();
    int base = (warp > 0) ? wsums[warp - 1] : 0;
    incl += base;
    if (i < N_NODES) g_off[i] = incl - d;
    if (t == SCAN_BLK - 1) g_bsum[blockIdx.x] = incl;
}

// ---------------------------------------------------------------------------
// K3b: scan the 65 block sums
// ---------------------------------------------------------------------------
__global__ __launch_bounds__(128) void scan2_kernel() {
    __shared__ int s[128];
    int t = threadIdx.x;
    s[t] = (t < NSCAN_BLOCKS) ? g_bsum[t] : 0;
    __syncthreads();
    for (int o = 1; o < 128; o <<= 1) {
        int v = (t >= o) ? s[t - o] : 0;
        __syncthreads();
        s[t] += v;
        __syncthreads();
    }
    if (t < NSCAN_BLOCKS) g_boff[t] = (t == 0) ? 0 : s[t - 1];
    if (t == 0) g_off[N_NODES] = E_EDGES;
}

// ---------------------------------------------------------------------------
// K3c: add block offsets, init cursors
// ---------------------------------------------------------------------------
__global__ __launch_bounds__(SCAN_BLK) void scan3_kernel() {
    int i = blockIdx.x * SCAN_BLK + threadIdx.x;
    if (i < N_NODES) {
        int v = g_off[i] + g_boff[blockIdx.x];
        g_off[i] = v;
        g_cur[i] = v;
    }
}

// ---------------------------------------------------------------------------
// K4: scatter src ids into dst buckets — 4 edges/thread via int4 loads.
// E_EDGES % 4 == 0.
// ---------------------------------------------------------------------------
__global__ void scatter_kernel(const int* __restrict__ src,
                               const int* __restrict__ dst) {
    int q = blockIdx.x * blockDim.x + threadIdx.x;
    if (q >= E_EDGES / 4) return;
    int4 s4 = ((const int4*)src)[q];
    int4 d4 = ((const int4*)dst)[q];
    int pos;
    pos = atomicAdd(&g_cur[d4.x], 1); g_csr_src[pos] = s4.x;
    pos = atomicAdd(&g_cur[d4.y], 1); g_csr_src[pos] = s4.y;
    pos = atomicAdd(&g_cur[d4.z], 1); g_csr_src[pos] = s4.z;
    pos = atomicAdd(&g_cur[d4.w], 1); g_csr_src[pos] = s4.w;
}

// ---------------------------------------------------------------------------
// K5: per-node gather, one warp per node. Serial phase explicitly batches 8
// edges: 8 LDS.128 + 8 independent LDG.64 issued front-to-back (MLP=8), then
// the FMA tail. Lanes 0-15 head 0, lanes 16-31 head 1.
// ---------------------------------------------------------------------------
__global__ __launch_bounds__(256) void gather_kernel(
    float* __restrict__ out,
    const float* __restrict__ bias)
{
    __shared__ float4 stage[8][32];     // 4 KB

    int wid_in_blk = threadIdx.x >> 5;
    int node = blockIdx.x * 8 + wid_in_blk;
    if (node >= N_NODES) return;
    int lane = threadIdx.x & 31;
    int head = lane >> 4;

    float2 ad2 = *(const float2*)(g_adst + (size_t)node * 2);
    float2 a2  = *(const float2*)(g_asrc + (size_t)node * 2);

    float e0s = a2.x + ad2.x; e0s = (e0s > 0.0f) ? e0s : NEG_SLOPE * e0s;
    float e1s = a2.y + ad2.y; e1s = (e1s > 0.0f) ? e1s : NEG_SLOPE * e1s;
    float exs0 = __expf(e0s);
    float exs1 = __expf(e1s);
    float exsh = head ? exs1 : exs0;

    uint2 raw0 = *(const uint2*)(g_h + (size_t)node * HC + lane * 4);
    __half2 p0 = *reinterpret_cast<__half2*>(&raw0.x);
    __half2 p1 = *reinterpret_cast<__half2*>(&raw0.y);
    float2 f0 = __half22float2(p0), f1 = __half22float2(p1);
    float4 acc = make_float4(f0.x * exsh, f0.y * exsh, f1.x * exsh, f1.y * exsh);

    float dsum0 = 0.0f, dsum1 = 0.0f;

    int start = g_off[node];
    int end   = g_off[node + 1];

    for (int j0 = start; j0 < end; j0 += 32) {
        int myj = j0 + lane;
        float ex0 = 0.0f, ex1 = 0.0f;
        int s = 0;
        if (myj < end) {
            s = g_csr_src[myj];
            float2 a = *(const float2*)(g_asrc + (size_t)s * 2);
            float e0 = a.x + ad2.x; e0 = (e0 > 0.0f) ? e0 : NEG_SLOPE * e0;
            float e1 = a.y + ad2.y; e1 = (e1 > 0.0f) ? e1 : NEG_SLOPE * e1;
            ex0 = __expf(e0);
            ex1 = __expf(e1);
        }
        dsum0 += ex0;
        dsum1 += ex1;
        stage[wid_in_blk][lane] = make_float4(ex0, ex1, __int_as_float(s), 0.0f);
        __syncwarp();

        int cnt = min(32, end - j0);
        int k = 0;
        // 8-wide batches: all 8 h-row loads in flight together
        for (; k + 8 <= cnt; k += 8) {
            float exh[8];
            uint2 raw[8];
            #pragma unroll
            for (int u = 0; u < 8; u++) {
                float4 t = stage[wid_in_blk][k + u];
                exh[u] = head ? t.y : t.x;
                int sk = __float_as_int(t.z);
                raw[u] = *(const uint2*)(g_h + (size_t)sk * HC + lane * 4);
            }
            #pragma unroll
            for (int u = 0; u < 8; u++) {
                __half2 q0 = *reinterpret_cast<__half2*>(&raw[u].x);
                __half2 q1 = *reinterpret_cast<__half2*>(&raw[u].y);
                float2 g0 = __half22float2(q0), g1 = __half22float2(q1);
                acc.x = fmaf(exh[u], g0.x, acc.x);
                acc.y = fmaf(exh[u], g0.y, acc.y);
                acc.z = fmaf(exh[u], g1.x, acc.z);
                acc.w = fmaf(exh[u], g1.y, acc.w);
            }
        }
        for (; k < cnt; k++) {
            float4 t = stage[wid_in_blk][k];
            float eh = head ? t.y : t.x;
            int   sk = __float_as_int(t.z);
            uint2 raw1 = *(const uint2*)(g_h + (size_t)sk * HC + lane * 4);
            __half2 q0 = *reinterpret_cast<__half2*>(&raw1.x);
            __half2 q1 = *reinterpret_cast<__half2*>(&raw1.y);
            float2 g0 = __half22float2(q0), g1 = __half22float2(q1);
            acc.x = fmaf(eh, g0.x, acc.x);
            acc.y = fmaf(eh, g0.y, acc.y);
            acc.z = fmaf(eh, g1.x, acc.z);
            acc.w = fmaf(eh, g1.y, acc.w);
        }
        __syncwarp();
    }

    #pragma unroll
    for (int o = 16; o > 0; o >>= 1) {
        dsum0 += __shfl_xor_sync(0xffffffffu, dsum0, o);
        dsum1 += __shfl_xor_sync(0xffffffffu, dsum1, o);
    }
    float den = head ? (dsum1 + exs1) : (dsum0 + exs0);

    float inv = 1.0f / (den + 1e-16f);
    float4 b = *(const float4*)(bias + lane * 4);
    float4 o = make_float4(acc.x * inv + b.x, acc.y * inv + b.y,
                           acc.z * inv + b.z, acc.w * inv + b.w);
    *(float4*)(out + (size_t)node * HC + lane * 4) = o;
}

// ---------------------------------------------------------------------------
// Inputs (metadata order): edge_index[2,E] i32, users_feature, items_feature,
//                          W, att_src, att_dst, bias   — all float32.
// ---------------------------------------------------------------------------
extern "C" void kernel_launch(void* const* d_in, const int* in_sizes, int n_in,
                              void* d_out, int out_size)
{
    const int*   edge_index = (const int*)d_in[0];
    const float* users      = (const float*)d_in[1];
    const float* items      = (const float*)d_in[2];
    const float* W          = (const float*)d_in[3];
    const float* att_src    = (const float*)d_in[4];
    const float* att_dst    = (const float*)d_in[5];
    const float* bias       = (const float*)d_in[6];
    float* out = (float*)d_out;

    const int* src = edge_index;
    const int* dst = edge_index + E_EDGES;

    gemm_count_kernel<<<GEMM_BLOCKS + COUNT_BLOCKS, 128>>>(
        users, items, W, att_src, att_dst, dst);

    scan1_kernel<<<NSCAN_BLOCKS, SCAN_BLK>>>();
    scan2_kernel<<<1, 128>>>();
    scan3_kernel<<<NSCAN_BLOCKS, SCAN_BLK>>>();

    int qblocks = (E_EDGES / 4 + 255) / 256;
    scatter_kernel<<<qblocks, 256>>>(src, dst);

    int gblocks = (N_NODES + 7) / 8;
    gather_kernel<<<gblocks, 256>>>(out, bias);
}

// round 16
// speedup vs baseline: 3.2222x; 1.1951x over previous
#include <cuda_runtime.h>
#include <cuda_fp16.h>

#define N_USERS 17449
#define N_ITEMS 48676
#define N_NODES (N_USERS + N_ITEMS)   // 66125
#define D_IN    64
#define HC      128                    // H*C = 2*64
#define E_EDGES 2000000
#define NEG_SLOPE 0.2f
#define SCAN_BLK 1024
#define NSCAN_BLOCKS ((N_NODES + SCAN_BLK - 1) / SCAN_BLK)   // 65

#define GROWS 8                                              // rows (warps) per gemm block
#define GEMM_BLOCKS ((N_NODES + GROWS - 1) / GROWS)          // 8266
#define COUNT_BLOCKS 2048

// Scratch (no cudaMalloc allowed): ~26 MB of __device__ globals.
// g_deg / g_ticket rely on zero-init at load; the scan kernel restores both
// after use so every graph replay is deterministic.
__device__ __half g_h[(size_t)N_NODES * HC];    // transformed features [N,128], fp16
__device__ float g_asrc[N_NODES * 2];           // per-node src logits [N,H]
__device__ float g_adst[N_NODES * 2];           // per-node dst logits [N,H]
__device__ int   g_deg[N_NODES];                // in-degree (excl. self loop)
__device__ int   g_off[N_NODES];                // CSR offsets, BLOCK-LOCAL exclusive
__device__ int   g_cur[N_NODES];                // scatter cursors, BLOCK-LOCAL
__device__ int   g_bsum[NSCAN_BLOCKS];          // per-scan-block degree sums
__device__ int   g_boff[NSCAN_BLOCKS];          // scanned block offsets
__device__ int   g_ticket;                      // last-block election counter
__device__ int   g_csr_src[E_EDGES];            // src id per edge, bucketed by dst

// ---------------------------------------------------------------------------
// K1: fused  (a) h = x @ W + logit reductions   (b) degree histogram.
// Gemm part: ONE WARP PER ROW, no syncthreads in the mainloop.
// Lane owns 4 consecutive output cols (4l..4l+3): LDS.128 of W, coalesced
// 8 B fp16 store of h. Logit halves (lanes 0-15 head0 / 16-31 head1) reduce
// via 4 butterflies.
// ---------------------------------------------------------------------------
__global__ __launch_bounds__(256) void gemm_count_kernel(
    const float* __restrict__ users,
    const float* __restrict__ items,
    const float* __restrict__ W,        // [64,128] row-major
    const float* __restrict__ att_src,  // [2,64] flattened = 128
    const float* __restrict__ att_dst,
    const int* __restrict__ dst)
{
    __shared__ float Ws[D_IN * HC];     // 32 KB

    if (blockIdx.x >= GEMM_BLOCKS) {
        // ---- degree histogram, int4-vectorized grid-stride ----
        int b = blockIdx.x - GEMM_BLOCKS;
        int stride = COUNT_BLOCKS * 256;
        const int4* dst4 = (const int4*)dst;
        for (int q = b * 256 + threadIdx.x; q < E_EDGES / 4; q += stride) {
            int4 d4 = dst4[q];
            atomicAdd(&g_deg[d4.x], 1);
            atomicAdd(&g_deg[d4.y], 1);
            atomicAdd(&g_deg[d4.z], 1);
            atomicAdd(&g_deg[d4.w], 1);
        }
        return;
    }

    int tid  = threadIdx.x;
    int warp = tid >> 5;
    int lane = tid & 31;

    for (int i = tid; i < D_IN * HC / 4; i += 256)
        ((float4*)Ws)[i] = ((const float4*)W)[i];
    float4 as4 = ((const float4*)att_src)[lane];   // cols 4l..4l+3
    float4 ad4 = ((const float4*)att_dst)[lane];
    __syncthreads();

    int n = blockIdx.x * GROWS + warp;
    if (n >= N_NODES) return;

    const float* xrow = (n < N_USERS) ? users + (size_t)n * D_IN
                                      : items + (size_t)(n - N_USERS) * D_IN;
    float2 xv = ((const float2*)xrow)[lane];       // x[2l], x[2l+1]

    float4 acc = make_float4(0.f, 0.f, 0.f, 0.f);
    #pragma unroll
    for (int kk = 0; kk < 32; kk++) {
        float xk0 = __shfl_sync(0xffffffffu, xv.x, kk);
        float xk1 = __shfl_sync(0xffffffffu, xv.y, kk);
        float4 w0 = ((const float4*)(Ws + (2 * kk)     * HC))[lane];
        float4 w1 = ((const float4*)(Ws + (2 * kk + 1) * HC))[lane];
        acc.x = fmaf(xk0, w0.x, acc.x);
        acc.y = fmaf(xk0, w0.y, acc.y);
        acc.z = fmaf(xk0, w0.z, acc.z);
        acc.w = fmaf(xk0, w0.w, acc.w);
        acc.x = fmaf(xk1, w1.x, acc.x);
        acc.y = fmaf(xk1, w1.y, acc.y);
        acc.z = fmaf(xk1, w1.z, acc.z);
        acc.w = fmaf(xk1, w1.w, acc.w);
    }

    // store h row: 4 halves = 8 B, coalesced across lanes
    __half2 h0 = __floats2half2_rn(acc.x, acc.y);
    __half2 h1 = __floats2half2_rn(acc.z, acc.w);
    uint2 hbits;
    hbits.x = *reinterpret_cast<unsigned int*>(&h0);
    hbits.y = *reinterpret_cast<unsigned int*>(&h1);
    *(uint2*)(g_h + (size_t)n * HC + lane * 4) = hbits;

    // per-head logits: lanes 0-15 hold head0 cols, 16-31 head1 cols
    float ps = acc.x * as4.x + acc.y * as4.y + acc.z * as4.z + acc.w * as4.w;
    float pd = acc.x * ad4.x + acc.y * ad4.y + acc.z * ad4.z + acc.w * ad4.w;
    #pragma unroll
    for (int o = 8; o > 0; o >>= 1) {
        ps += __shfl_xor_sync(0xffffffffu, ps, o);
        pd += __shfl_xor_sync(0xffffffffu, pd, o);
    }
    if (lane == 0)  { g_asrc[n * 2 + 0] = ps; g_adst[n * 2 + 0] = pd; }
    if (lane == 16) { g_asrc[n * 2 + 1] = ps; g_adst[n * 2 + 1] = pd; }
}

// ---------------------------------------------------------------------------
// K2: fused scan. Per-block exclusive scan of degrees (block-local values in
// g_off/g_cur), block sums to g_bsum; the LAST block (atomic ticket) scans
// the 65 block sums into g_boff. Consumers add g_boff[i>>10].
// Also re-zeroes g_deg and resets g_ticket for the next graph replay.
// ---------------------------------------------------------------------------
__global__ __launch_bounds__(SCAN_BLK) void scan_kernel() {
    __shared__ int wsums[32];
    __shared__ int s2[128];
    __shared__ int is_last_s;

    int t = threadIdx.x;
    int i = blockIdx.x * SCAN_BLK + t;
    int d = (i < N_NODES) ? g_deg[i] : 0;
    if (i < N_NODES) g_deg[i] = 0;

    int lane = t & 31, warp = t >> 5;
    int incl = d;
    #pragma unroll
    for (int o = 1; o < 32; o <<= 1) {
        int v = __shfl_up_sync(0xffffffffu, incl, o);
        if (lane >= o) incl += v;
    }
    if (lane == 31) wsums[warp] = incl;
    __syncthreads();
    if (warp == 0) {
        int v = (lane < 32) ? wsums[lane] : 0;
        #pragma unroll
        for (int o = 1; o < 32; o <<= 1) {
            int u = __shfl_up_sync(0xffffffffu, v, o);
            if (lane >= o) v += u;
        }
        wsums[lane] = v;
    }
    __syncthreads();
    int base = (warp > 0) ? wsums[warp - 1] : 0;
    incl += base;
    int excl = incl - d;
    if (i < N_NODES) { g_off[i] = excl; g_cur[i] = excl; }
    if (t == SCAN_BLK - 1) g_bsum[blockIdx.x] = incl;

    // ---- last-block election ----
    __threadfence();
    if (t == 0)
        is_last_s = (atomicAdd(&g_ticket, 1) == NSCAN_BLOCKS - 1) ? 1 : 0;
    __syncthreads();
    if (!is_last_s) return;

    if (t == 0) g_ticket = 0;   // reset for next replay
    if (t < 128) s2[t] = (t < NSCAN_BLOCKS) ? g_bsum[t] : 0;
    __syncthreads();
    for (int o = 1; o < 128; o <<= 1) {
        int v = (t >= o && t < 128) ? s2[t - o] : 0;
        __syncthreads();
        if (t < 128) s2[t] += v;
        __syncthreads();
    }
    if (t < NSCAN_BLOCKS) g_boff[t] = (t == 0) ? 0 : s2[t - 1];
}

// ---------------------------------------------------------------------------
// K3: scatter src ids into dst buckets — 4 edges/thread via int4 loads.
// final pos = block-local cursor + g_boff[d>>10] (tiny L1-resident array).
// ---------------------------------------------------------------------------
__global__ void scatter_kernel(const int* __restrict__ src,
                               const int* __restrict__ dst) {
    int q = blockIdx.x * blockDim.x + threadIdx.x;
    if (q >= E_EDGES / 4) return;
    int4 s4 = ((const int4*)src)[q];
    int4 d4 = ((const int4*)dst)[q];
    int pos;
    pos = atomicAdd(&g_cur[d4.x], 1) + g_boff[d4.x >> 10]; g_csr_src[pos] = s4.x;
    pos = atomicAdd(&g_cur[d4.y], 1) + g_boff[d4.y >> 10]; g_csr_src[pos] = s4.y;
    pos = atomicAdd(&g_cur[d4.z], 1) + g_boff[d4.z >> 10]; g_csr_src[pos] = s4.z;
    pos = atomicAdd(&g_cur[d4.w], 1) + g_boff[d4.w >> 10]; g_csr_src[pos] = s4.w;
}

// ---------------------------------------------------------------------------
// K4: per-node gather, one warp per node. Serial phase batches 8 edges
// (8 LDS.128 + 8 independent LDG.64, MLP=8) then the FMA tail.
// Lanes 0-15 head 0, lanes 16-31 head 1.
// ---------------------------------------------------------------------------
__global__ __launch_bounds__(256) void gather_kernel(
    float* __restrict__ out,
    const float* __restrict__ bias)
{
    __shared__ float4 stage[8][32];     // 4 KB

    int wid_in_blk = threadIdx.x >> 5;
    int node = blockIdx.x * 8 + wid_in_blk;
    if (node >= N_NODES) return;
    int lane = threadIdx.x & 31;
    int head = lane >> 4;

    float2 ad2 = *(const float2*)(g_adst + (size_t)node * 2);
    float2 a2  = *(const float2*)(g_asrc + (size_t)node * 2);

    float e0s = a2.x + ad2.x; e0s = (e0s > 0.0f) ? e0s : NEG_SLOPE * e0s;
    float e1s = a2.y + ad2.y; e1s = (e1s > 0.0f) ? e1s : NEG_SLOPE * e1s;
    float exs0 = __expf(e0s);
    float exs1 = __expf(e1s);
    float exsh = head ? exs1 : exs0;

    uint2 raw0 = *(const uint2*)(g_h + (size_t)node * HC + lane * 4);
    __half2 p0 = *reinterpret_cast<__half2*>(&raw0.x);
    __half2 p1 = *reinterpret_cast<__half2*>(&raw0.y);
    float2 f0 = __half22float2(p0), f1 = __half22float2(p1);
    float4 acc = make_float4(f0.x * exsh, f0.y * exsh, f1.x * exsh, f1.y * exsh);

    float dsum0 = 0.0f, dsum1 = 0.0f;

    int start = g_off[node] + g_boff[node >> 10];
    int nxt = node + 1;
    int end = (nxt < N_NODES) ? (g_off[nxt] + g_boff[nxt >> 10]) : E_EDGES;

    for (int j0 = start; j0 < end; j0 += 32) {
        int myj = j0 + lane;
        float ex0 = 0.0f, ex1 = 0.0f;
        int s = 0;
        if (myj < end) {
            s = g_csr_src[myj];
            float2 a = *(const float2*)(g_asrc + (size_t)s * 2);
            float e0 = a.x + ad2.x; e0 = (e0 > 0.0f) ? e0 : NEG_SLOPE * e0;
            float e1 = a.y + ad2.y; e1 = (e1 > 0.0f) ? e1 : NEG_SLOPE * e1;
            ex0 = __expf(e0);
            ex1 = __expf(e1);
        }
        dsum0 += ex0;
        dsum1 += ex1;
        stage[wid_in_blk][lane] = make_float4(ex0, ex1, __int_as_float(s), 0.0f);
        __syncwarp();

        int cnt = min(32, end - j0);
        int k = 0;
        for (; k + 8 <= cnt; k += 8) {
            float exh[8];
            uint2 raw[8];
            #pragma unroll
            for (int u = 0; u < 8; u++) {
                float4 t = stage[wid_in_blk][k + u];
                exh[u] = head ? t.y : t.x;
                int sk = __float_as_int(t.z);
                raw[u] = *(const uint2*)(g_h + (size_t)sk * HC + lane * 4);
            }
            #pragma unroll
            for (int u = 0; u < 8; u++) {
                __half2 q0 = *reinterpret_cast<__half2*>(&raw[u].x);
                __half2 q1 = *reinterpret_cast<__half2*>(&raw[u].y);
                float2 g0 = __half22float2(q0), g1 = __half22float2(q1);
                acc.x = fmaf(exh[u], g0.x, acc.x);
                acc.y = fmaf(exh[u], g0.y, acc.y);
                acc.z = fmaf(exh[u], g1.x, acc.z);
                acc.w = fmaf(exh[u], g1.y, acc.w);
            }
        }
        for (; k < cnt; k++) {
            float4 t = stage[wid_in_blk][k];
            float eh = head ? t.y : t.x;
            int   sk = __float_as_int(t.z);
            uint2 raw1 = *(const uint2*)(g_h + (size_t)sk * HC + lane * 4);
            __half2 q0 = *reinterpret_cast<__half2*>(&raw1.x);
            __half2 q1 = *reinterpret_cast<__half2*>(&raw1.y);
            float2 g0 = __half22float2(q0), g1 = __half22float2(q1);
            acc.x = fmaf(eh, g0.x, acc.x);
            acc.y = fmaf(eh, g0.y, acc.y);
            acc.z = fmaf(eh, g1.x, acc.z);
            acc.w = fmaf(eh, g1.y, acc.w);
        }
        __syncwarp();
    }

    #pragma unroll
    for (int o = 16; o > 0; o >>= 1) {
        dsum0 += __shfl_xor_sync(0xffffffffu, dsum0, o);
        dsum1 += __shfl_xor_sync(0xffffffffu, dsum1, o);
    }
    float den = head ? (dsum1 + exs1) : (dsum0 + exs0);

    float inv = 1.0f / (den + 1e-16f);
    float4 b = *(const float4*)(bias + lane * 4);
    float4 o = make_float4(acc.x * inv + b.x, acc.y * inv + b.y,
                           acc.z * inv + b.z, acc.w * inv + b.w);
    *(float4*)(out + (size_t)node * HC + lane * 4) = o;
}

// ---------------------------------------------------------------------------
// Inputs (metadata order): edge_index[2,E] i32, users_feature, items_feature,
//                          W, att_src, att_dst, bias   — all float32.
// ---------------------------------------------------------------------------
extern "C" void kernel_launch(void* const* d_in, const int* in_sizes, int n_in,
                              void* d_out, int out_size)
{
    const int*   edge_index = (const int*)d_in[0];
    const float* users      = (const float*)d_in[1];
    const float* items      = (const float*)d_in[2];
    const float* W          = (const float*)d_in[3];
    const float* att_src    = (const float*)d_in[4];
    const float* att_dst    = (const float*)d_in[5];
    const float* bias       = (const float*)d_in[6];
    float* out = (float*)d_out;

    const int* src = edge_index;
    const int* dst = edge_index + E_EDGES;

    gemm_count_kernel<<<GEMM_BLOCKS + COUNT_BLOCKS, 256>>>(
        users, items, W, att_src, att_dst, dst);

    scan_kernel<<<NSCAN_BLOCKS, SCAN_BLK>>>();

    int qblocks = (E_EDGES / 4 + 255) / 256;
    scatter_kernel<<<qblocks, 256>>>(src, dst);

    int gblocks = (N_NODES + 7) / 8;
    gather_kernel<<<gblocks, 256>>>(out, bias);
}

// round 17
// speedup vs baseline: 4.5736x; 1.4194x over previous
#include <cuda_runtime.h>
#include <cuda_fp16.h>

#define N_USERS 17449
#define N_ITEMS 48676
#define N_NODES (N_USERS + N_ITEMS)   // 66125
#define D_IN    64
#define HC      128                    // H*C = 2*64
#define E_EDGES 2000000
#define NEG_SLOPE 0.2f
#define SCAN_BLK 1024
#define NSCAN_BLOCKS ((N_NODES + SCAN_BLK - 1) / SCAN_BLK)   // 65

#define GROWS 32                                             // rows per gemm block (4 per warp)
#define GEMM_BLOCKS ((N_NODES + GROWS - 1) / GROWS)          // 2067
#define COUNT_BLOCKS 2048

// Scratch (~34 MB of __device__ globals; no cudaMalloc allowed).
// g_deg / g_ticket rely on zero-init at load; scan restores both per replay.
__device__ __half g_h[(size_t)N_NODES * HC];    // transformed features, fp16
__device__ float g_asrc[N_NODES * 2];           // per-node src logits [N,H]
__device__ float g_adst[N_NODES * 2];           // per-node dst logits [N,H]
__device__ int   g_deg[N_NODES];                // in-degree (excl. self loop)
__device__ int   g_off[N_NODES];                // CSR offsets, BLOCK-LOCAL exclusive
__device__ int   g_bsum[NSCAN_BLOCKS];          // per-scan-block degree sums
__device__ int   g_boff[NSCAN_BLOCKS];          // scanned block offsets
__device__ int   g_ticket;                      // last-block election counter
__device__ int   g_rank[E_EDGES];               // edge's rank within its dst bucket
__device__ int   g_csr_src[E_EDGES];            // src id per edge, bucketed by dst

// ---------------------------------------------------------------------------
// K1: fused  (a) h = x @ W + logit reductions   (b) degree histogram + ranks.
// Gemm: 8 warps/block, 4 rows per warp, x staged in smem, k chunked by 4.
// W is loaded once per 32 rows (was once per 8) -> 4x less L2 traffic.
// Count: atomicAdd RETURN is the edge's rank within its dst bucket; stored
// int4-coalesced so the scatter pass needs no atomics at all.
// ---------------------------------------------------------------------------
__global__ __launch_bounds__(256) void gemm_count_kernel(
    const float* __restrict__ users,
    const float* __restrict__ items,
    const float* __restrict__ W,        // [64,128] row-major
    const float* __restrict__ att_src,  // [2,64] flattened = 128
    const float* __restrict__ att_dst,
    const int* __restrict__ dst)
{
    __shared__ float Ws[D_IN * HC];     // 32 KB
    __shared__ float Xs[GROWS * D_IN];  // 8 KB

    if (blockIdx.x >= GEMM_BLOCKS) {
        // ---- degree histogram + rank record, int4-vectorized grid-stride ----
        int b = blockIdx.x - GEMM_BLOCKS;
        int stride = COUNT_BLOCKS * 256;
        const int4* dst4 = (const int4*)dst;
        for (int q = b * 256 + threadIdx.x; q < E_EDGES / 4; q += stride) {
            int4 d4 = dst4[q];
            int4 r4;
            r4.x = atomicAdd(&g_deg[d4.x], 1);
            r4.y = atomicAdd(&g_deg[d4.y], 1);
            r4.z = atomicAdd(&g_deg[d4.z], 1);
            r4.w = atomicAdd(&g_deg[d4.w], 1);
            ((int4*)g_rank)[q] = r4;
        }
        return;
    }

    int tid  = threadIdx.x;
    int warp = tid >> 5;
    int lane = tid & 31;
    int row0 = blockIdx.x * GROWS;

    for (int i = tid; i < D_IN * HC / 4; i += 256)
        ((float4*)Ws)[i] = ((const float4*)W)[i];

    // stage 32 x-rows (zero-padded past N_NODES)
    for (int i = tid; i < GROWS * (D_IN / 4); i += 256) {
        int r = i >> 4;              // row in block
        int c = i & 15;              // float4 column
        int n = row0 + r;
        float4 v = make_float4(0.f, 0.f, 0.f, 0.f);
        if (n < N_NODES) {
            const float* xrow = (n < N_USERS) ? users + (size_t)n * D_IN
                                              : items + (size_t)(n - N_USERS) * D_IN;
            v = ((const float4*)xrow)[c];
        }
        ((float4*)Xs)[i] = v;
    }
    float4 as4 = ((const float4*)att_src)[lane];   // cols 4l..4l+3
    float4 ad4 = ((const float4*)att_dst)[lane];
    __syncthreads();

    const float* xbase = Xs + warp * 4 * D_IN;
    float4 acc[4];
    #pragma unroll
    for (int r = 0; r < 4; r++) acc[r] = make_float4(0.f, 0.f, 0.f, 0.f);

    #pragma unroll 4
    for (int c4 = 0; c4 < D_IN / 4; c4++) {
        float4 w0 = ((const float4*)(Ws + (4 * c4 + 0) * HC))[lane];
        float4 w1 = ((const float4*)(Ws + (4 * c4 + 1) * HC))[lane];
        float4 w2 = ((const float4*)(Ws + (4 * c4 + 2) * HC))[lane];
        float4 w3 = ((const float4*)(Ws + (4 * c4 + 3) * HC))[lane];
        #pragma unroll
        for (int r = 0; r < 4; r++) {
            float4 xc = ((const float4*)(xbase + r * D_IN))[c4];  // broadcast LDS
            acc[r].x = fmaf(xc.x, w0.x, acc[r].x);
            acc[r].y = fmaf(xc.x, w0.y, acc[r].y);
            acc[r].z = fmaf(xc.x, w0.z, acc[r].z);
            acc[r].w = fmaf(xc.x, w0.w, acc[r].w);
            acc[r].x = fmaf(xc.y, w1.x, acc[r].x);
            acc[r].y = fmaf(xc.y, w1.y, acc[r].y);
            acc[r].z = fmaf(xc.y, w1.z, acc[r].z);
            acc[r].w = fmaf(xc.y, w1.w, acc[r].w);
            acc[r].x = fmaf(xc.z, w2.x, acc[r].x);
            acc[r].y = fmaf(xc.z, w2.y, acc[r].y);
            acc[r].z = fmaf(xc.z, w2.z, acc[r].z);
            acc[r].w = fmaf(xc.z, w2.w, acc[r].w);
            acc[r].x = fmaf(xc.w, w3.x, acc[r].x);
            acc[r].y = fmaf(xc.w, w3.y, acc[r].y);
            acc[r].z = fmaf(xc.w, w3.z, acc[r].z);
            acc[r].w = fmaf(xc.w, w3.w, acc[r].w);
        }
    }

    #pragma unroll
    for (int r = 0; r < 4; r++) {
        int n = row0 + warp * 4 + r;
        if (n >= N_NODES) break;

        __half2 h0 = __floats2half2_rn(acc[r].x, acc[r].y);
        __half2 h1 = __floats2half2_rn(acc[r].z, acc[r].w);
        uint2 hbits;
        hbits.x = *reinterpret_cast<unsigned int*>(&h0);
        hbits.y = *reinterpret_cast<unsigned int*>(&h1);
        *(uint2*)(g_h + (size_t)n * HC + lane * 4) = hbits;

        float ps = acc[r].x * as4.x + acc[r].y * as4.y + acc[r].z * as4.z + acc[r].w * as4.w;
        float pd = acc[r].x * ad4.x + acc[r].y * ad4.y + acc[r].z * ad4.z + acc[r].w * ad4.w;
        #pragma unroll
        for (int o = 8; o > 0; o >>= 1) {
            ps += __shfl_xor_sync(0xffffffffu, ps, o);
            pd += __shfl_xor_sync(0xffffffffu, pd, o);
        }
        if (lane == 0)  { g_asrc[n * 2 + 0] = ps; g_adst[n * 2 + 0] = pd; }
        if (lane == 16) { g_asrc[n * 2 + 1] = ps; g_adst[n * 2 + 1] = pd; }
    }
}

// ---------------------------------------------------------------------------
// K2: fused scan (unchanged except g_cur removed). Block-local exclusive
// offsets in g_off; last block (atomic ticket) scans the 65 block sums.
// Re-zeroes g_deg + resets g_ticket for the next graph replay.
// ---------------------------------------------------------------------------
__global__ __launch_bounds__(SCAN_BLK) void scan_kernel() {
    __shared__ int wsums[32];
    __shared__ int s2[128];
    __shared__ int is_last_s;

    int t = threadIdx.x;
    int i = blockIdx.x * SCAN_BLK + t;
    int d = (i < N_NODES) ? g_deg[i] : 0;
    if (i < N_NODES) g_deg[i] = 0;

    int lane = t & 31, warp = t >> 5;
    int incl = d;
    #pragma unroll
    for (int o = 1; o < 32; o <<= 1) {
        int v = __shfl_up_sync(0xffffffffu, incl, o);
        if (lane >= o) incl += v;
    }
    if (lane == 31) wsums[warp] = incl;
    __syncthreads();
    if (warp == 0) {
        int v = (lane < 32) ? wsums[lane] : 0;
        #pragma unroll
        for (int o = 1; o < 32; o <<= 1) {
            int u = __shfl_up_sync(0xffffffffu, v, o);
            if (lane >= o) v += u;
        }
        wsums[lane] = v;
    }
    __syncthreads();
    int base = (warp > 0) ? wsums[warp - 1] : 0;
    incl += base;
    if (i < N_NODES) g_off[i] = incl - d;
    if (t == SCAN_BLK - 1) g_bsum[blockIdx.x] = incl;

    __threadfence();
    if (t == 0)
        is_last_s = (atomicAdd(&g_ticket, 1) == NSCAN_BLOCKS - 1) ? 1 : 0;
    __syncthreads();
    if (!is_last_s) return;

    if (t == 0) g_ticket = 0;
    if (t < 128) s2[t] = (t < NSCAN_BLOCKS) ? g_bsum[t] : 0;
    __syncthreads();
    for (int o = 1; o < 128; o <<= 1) {
        int v = (t >= o && t < 128) ? s2[t - o] : 0;
        __syncthreads();
        if (t < 128) s2[t] += v;
        __syncthreads();
    }
    if (t < NSCAN_BLOCKS) g_boff[t] = (t == 0) ? 0 : s2[t - 1];
}

// ---------------------------------------------------------------------------
// K3: ATOMIC-FREE scatter: pos = off[d] + boff[d>>10] + rank.
// Pure streaming int4 reads (src, dst, rank) + cached off/boff lookups.
// ---------------------------------------------------------------------------
__global__ void scatter_kernel(const int* __restrict__ src,
                               const int* __restrict__ dst) {
    int q = blockIdx.x * blockDim.x + threadIdx.x;
    if (q >= E_EDGES / 4) return;
    int4 s4 = ((const int4*)src)[q];
    int4 d4 = ((const int4*)dst)[q];
    int4 r4 = ((const int4*)g_rank)[q];
    g_csr_src[g_off[d4.x] + g_boff[d4.x >> 10] + r4.x] = s4.x;
    g_csr_src[g_off[d4.y] + g_boff[d4.y >> 10] + r4.y] = s4.y;
    g_csr_src[g_off[d4.z] + g_boff[d4.z >> 10] + r4.z] = s4.z;
    g_csr_src[g_off[d4.w] + g_boff[d4.w >> 10] + r4.w] = s4.w;
}

// ---------------------------------------------------------------------------
// K4: per-node gather, one warp per node (unchanged from R16 — measured at
// its issue-bound plateau). Lanes 0-15 head 0, lanes 16-31 head 1.
// ---------------------------------------------------------------------------
__global__ __launch_bounds__(256) void gather_kernel(
    float* __restrict__ out,
    const float* __restrict__ bias)
{
    __shared__ float4 stage[8][32];     // 4 KB

    int wid_in_blk = threadIdx.x >> 5;
    int node = blockIdx.x * 8 + wid_in_blk;
    if (node >= N_NODES) return;
    int lane = threadIdx.x & 31;
    int head = lane >> 4;

    float2 ad2 = *(const float2*)(g_adst + (size_t)node * 2);
    float2 a2  = *(const float2*)(g_asrc + (size_t)node * 2);

    float e0s = a2.x + ad2.x; e0s = (e0s > 0.0f) ? e0s : NEG_SLOPE * e0s;
    float e1s = a2.y + ad2.y; e1s = (e1s > 0.0f) ? e1s : NEG_SLOPE * e1s;
    float exs0 = __expf(e0s);
    float exs1 = __expf(e1s);
    float exsh = head ? exs1 : exs0;

    uint2 raw0 = *(const uint2*)(g_h + (size_t)node * HC + lane * 4);
    __half2 p0 = *reinterpret_cast<__half2*>(&raw0.x);
    __half2 p1 = *reinterpret_cast<__half2*>(&raw0.y);
    float2 f0 = __half22float2(p0), f1 = __half22float2(p1);
    float4 acc = make_float4(f0.x * exsh, f0.y * exsh, f1.x * exsh, f1.y * exsh);

    float dsum0 = 0.0f, dsum1 = 0.0f;

    int start = g_off[node] + g_boff[node >> 10];
    int nxt = node + 1;
    int end = (nxt < N_NODES) ? (g_off[nxt] + g_boff[nxt >> 10]) : E_EDGES;

    for (int j0 = start; j0 < end; j0 += 32) {
        int myj = j0 + lane;
        float ex0 = 0.0f, ex1 = 0.0f;
        int s = 0;
        if (myj < end) {
            s = g_csr_src[myj];
            float2 a = *(const float2*)(g_asrc + (size_t)s * 2);
            float e0 = a.x + ad2.x; e0 = (e0 > 0.0f) ? e0 : NEG_SLOPE * e0;
            float e1 = a.y + ad2.y; e1 = (e1 > 0.0f) ? e1 : NEG_SLOPE * e1;
            ex0 = __expf(e0);
            ex1 = __expf(e1);
        }
        dsum0 += ex0;
        dsum1 += ex1;
        stage[wid_in_blk][lane] = make_float4(ex0, ex1, __int_as_float(s), 0.0f);
        __syncwarp();

        int cnt = min(32, end - j0);
        int k = 0;
        for (; k + 8 <= cnt; k += 8) {
            float exh[8];
            uint2 raw[8];
            #pragma unroll
            for (int u = 0; u < 8; u++) {
                float4 t = stage[wid_in_blk][k + u];
                exh[u] = head ? t.y : t.x;
                int sk = __float_as_int(t.z);
                raw[u] = *(const uint2*)(g_h + (size_t)sk * HC + lane * 4);
            }
            #pragma unroll
            for (int u = 0; u < 8; u++) {
                __half2 q0 = *reinterpret_cast<__half2*>(&raw[u].x);
                __half2 q1 = *reinterpret_cast<__half2*>(&raw[u].y);
                float2 g0 = __half22float2(q0), g1 = __half22float2(q1);
                acc.x = fmaf(exh[u], g0.x, acc.x);
                acc.y = fmaf(exh[u], g0.y, acc.y);
                acc.z = fmaf(exh[u], g1.x, acc.z);
                acc.w = fmaf(exh[u], g1.y, acc.w);
            }
        }
        for (; k < cnt; k++) {
            float4 t = stage[wid_in_blk][k];
            float eh = head ? t.y : t.x;
            int   sk = __float_as_int(t.z);
            uint2 raw1 = *(const uint2*)(g_h + (size_t)sk * HC + lane * 4);
            __half2 q0 = *reinterpret_cast<__half2*>(&raw1.x);
            __half2 q1 = *reinterpret_cast<__half2*>(&raw1.y);
            float2 g0 = __half22float2(q0), g1 = __half22float2(q1);
            acc.x = fmaf(eh, g0.x, acc.x);
            acc.y = fmaf(eh, g0.y, acc.y);
            acc.z = fmaf(eh, g1.x, acc.z);
            acc.w = fmaf(eh, g1.y, acc.w);
        }
        __syncwarp();
    }

    #pragma unroll
    for (int o = 16; o > 0; o >>= 1) {
        dsum0 += __shfl_xor_sync(0xffffffffu, dsum0, o);
        dsum1 += __shfl_xor_sync(0xffffffffu, dsum1, o);
    }
    float den = head ? (dsum1 + exs1) : (dsum0 + exs0);

    float inv = 1.0f / (den + 1e-16f);
    float4 b = *(const float4*)(bias + lane * 4);
    float4 o = make_float4(acc.x * inv + b.x, acc.y * inv + b.y,
                           acc.z * inv + b.z, acc.w * inv + b.w);
    *(float4*)(out + (size_t)node * HC + lane * 4) = o;
}

// ---------------------------------------------------------------------------
// Inputs (metadata order): edge_index[2,E] i32, users_feature, items_feature,
//                          W, att_src, att_dst, bias   — all float32.
// ---------------------------------------------------------------------------
extern "C" void kernel_launch(void* const* d_in, const int* in_sizes, int n_in,
                              void* d_out, int out_size)
{
    const int*   edge_index = (const int*)d_in[0];
    const float* users      = (const float*)d_in[1];
    const float* items      = (const float*)d_in[2];
    const float* W          = (const float*)d_in[3];
    const float* att_src    = (const float*)d_in[4];
    const float* att_dst    = (const float*)d_in[5];
    const float* bias       = (const float*)d_in[6];
    float* out = (float*)d_out;

    const int* src = edge_index;
    const int* dst = edge_index + E_EDGES;

    gemm_count_kernel<<<GEMM_BLOCKS + COUNT_BLOCKS, 256>>>(
        users, items, W, att_src, att_dst, dst);

    scan_kernel<<<NSCAN_BLOCKS, SCAN_BLK>>>();

    int qblocks = (E_EDGES / 4 + 255) / 256;
    scatter_kernel<<<qblocks, 256>>>(src, dst);

    int gblocks = (N_NODES + 7) / 8;
    gather_kernel<<<gblocks, 256>>>(out, bias);
}